// round 3
// baseline (speedup 1.0000x reference)
#include <cuda_runtime.h>

#define TPB        256
#define DMODEL     1024
#define NEXP       8
#define TOKENS_TOT 32768
#define NBLOCKS    2048
#define TPBLK      16        // tokens per block: 2048*16 = 32768

// ---------- packed fp32x2 helpers (sm_103a FFMA2 path) ----------
__device__ __forceinline__ unsigned long long pack2(float lo, float hi) {
    unsigned long long d;
    asm("mov.b64 %0, {%1, %2};" : "=l"(d) : "f"(lo), "f"(hi));
    return d;
}
__device__ __forceinline__ void unpack2(unsigned long long v, float& lo, float& hi) {
    asm("mov.b64 {%0, %1}, %2;" : "=f"(lo), "=f"(hi) : "l"(v));
}
__device__ __forceinline__ unsigned long long ffma2(unsigned long long a,
                                                    unsigned long long b,
                                                    unsigned long long c) {
    unsigned long long d;
    asm("fma.rn.f32x2 %0, %1, %2, %3;" : "=l"(d) : "l"(a), "l"(b), "l"(c));
    return d;
}

// Block of 256 threads; thread t owns dims [4t, 4t+4) of the 1024-dim row and
// keeps W[e][4t..4t+3] for all 8 experts in registers. Per token: 1 LDG.128 +
// 16 FFMA2 per thread, 9-shfl warp reduce, 1 STS/warp, 1 barrier, rotating
// 8-lane epilogue (bias + top2 + softmax + scatter).
__global__ void __launch_bounds__(TPB)
gating_kernel(const float* __restrict__ x, const float* __restrict__ W,
              const float* __restrict__ b, float* __restrict__ out_w,
              float* __restrict__ out_i, int write_idx)
{
    __shared__ float red[2][64];   // [buf][expert*8 + warp]

    const int tid  = threadIdx.x;
    const int lane = tid & 31;
    const int wid  = tid >> 5;

    // Resident W slice: 8 experts x 4 dims, as f32x2 pairs (32 regs).
    unsigned long long wlo[NEXP], whi[NEXP];
#pragma unroll
    for (int e = 0; e < NEXP; e++) {
        float4 wv = *(const float4*)(W + e * DMODEL + tid * 4);
        wlo[e] = pack2(wv.x, wv.y);
        whi[e] = pack2(wv.z, wv.w);
    }
    const float bval = b[lane & 7];

    const int t0 = blockIdx.x * TPBLK;
    const float4* xp = (const float4*)x + (size_t)t0 * (DMODEL / 4) + tid;

    // Depth-2 prefetch (TPBLK >= 2 always).
    float4 xa = xp[0];
    float4 xb = xp[256];

#pragma unroll 1
    for (int i = 0; i < TPBLK; i++) {
        const unsigned long long xlo = pack2(xa.x, xa.y);
        const unsigned long long xhi = pack2(xa.z, xa.w);
        xa = xb;
        if (i + 2 < TPBLK) xb = xp[(size_t)(i + 2) * 256];

        // 8 independent 2-deep FFMA2 chains.
        float s[NEXP];
#pragma unroll
        for (int e = 0; e < NEXP; e++) {
            unsigned long long acc = ffma2(xlo, wlo[e], 0ull);
            acc = ffma2(xhi, whi[e], acc);
            float lo, hi; unpack2(acc, lo, hi);
            s[e] = lo + hi;
        }

        // 9-shuffle reduce: split expert set across lane bits 4,3,2, then
        // plain reduce over lane bits 1,0. Lane ends with the full warp sum
        // for expert e_own = (lane>>2) & 7 (replicated over 4 lanes).
        const bool h16 = (lane & 16) != 0;
#pragma unroll
        for (int v = 0; v < 4; v++) {
            float send = h16 ? s[v] : s[v + 4];
            float recv = __shfl_xor_sync(0xFFFFFFFFu, send, 16);
            s[v] = (h16 ? s[v + 4] : s[v]) + recv;
        }
        const bool h8 = (lane & 8) != 0;
#pragma unroll
        for (int v = 0; v < 2; v++) {
            float send = h8 ? s[v] : s[v + 2];
            float recv = __shfl_xor_sync(0xFFFFFFFFu, send, 8);
            s[v] = (h8 ? s[v + 2] : s[v]) + recv;
        }
        {
            const bool h4 = (lane & 4) != 0;
            float send = h4 ? s[0] : s[1];
            float recv = __shfl_xor_sync(0xFFFFFFFFu, send, 4);
            s[0] = (h4 ? s[1] : s[0]) + recv;
        }
        float r = s[0];
        r += __shfl_xor_sync(0xFFFFFFFFu, r, 2);
        r += __shfl_xor_sync(0xFFFFFFFFu, r, 1);

        const int buf = i & 1;
        if ((lane & 3) == 0)
            red[buf][(((lane >> 2) & 7) << 3) + wid] = r;
        __syncthreads();

        // Rotating epilogue warp; lanes 8..31 mirror lanes 0..7.
        if (wid == (i & 7)) {
            const int e = lane & 7;
            const float* rb = red[buf] + (e << 3);
            float L = bval;
#pragma unroll
            for (int w = 0; w < 8; w++) L += rb[w];

            // top-1 with lowest-index tie-break (matches lax.top_k)
            float v1 = L; int i1 = e;
#pragma unroll
            for (int d = 1; d < 8; d <<= 1) {
                float vo = __shfl_xor_sync(0xFFFFFFFFu, v1, d);
                int   io = __shfl_xor_sync(0xFFFFFFFFu, i1, d);
                if (vo > v1 || (vo == v1 && io < i1)) { v1 = vo; i1 = io; }
            }
            // top-2: mask out i1
            float v2 = (e == i1) ? __int_as_float(0xff800000) : L;
            int   i2 = e;
#pragma unroll
            for (int d = 1; d < 8; d <<= 1) {
                float vo = __shfl_xor_sync(0xFFFFFFFFu, v2, d);
                int   io = __shfl_xor_sync(0xFFFFFFFFu, i2, d);
                if (vo > v2 || (vo == v2 && io < i2)) { v2 = vo; i2 = io; }
            }

            const float t   = __expf(v2 - v1);     // v2 <= v1, so t in (0,1]
            const float inv = 1.0f / (1.0f + t);
            const int token = t0 + i;
            if (lane < 8) {
                float wgt = (e == i1) ? inv : ((e == i2) ? t * inv : 0.0f);
                out_w[token * 8 + e] = wgt;
            }
            if (lane == 0 && write_idx) {
                float2 ii = make_float2((float)i1, (float)i2);
                *(float2*)(out_i + token * 2) = ii;
            }
        }
    }
}

extern "C" void kernel_launch(void* const* d_in, const int* in_sizes, int n_in,
                              void* d_out, int out_size)
{
    // Identify inputs by element count (metadata order: x, W, b).
    const float* x = nullptr; const float* W = nullptr; const float* b = nullptr;
    for (int i = 0; i < n_in; i++) {
        if (in_sizes[i] == NEXP)                b = (const float*)d_in[i];
        else if (in_sizes[i] == NEXP * DMODEL)  W = (const float*)d_in[i];
        else                                    x = (const float*)d_in[i];
    }

    float* ow = (float*)d_out;                       // weights: [B,S,E] f32
    float* oi = ow + (size_t)TOKENS_TOT * NEXP;      // indices as float: [B,S,2]
    const int need = TOKENS_TOT * NEXP + TOKENS_TOT * 2;
    const int write_idx = (out_size >= need) ? 1 : 0;

    gating_kernel<<<NBLOCKS, TPB>>>(x, W, b, ow, oi, write_idx);
}

// round 5
// speedup vs baseline: 1.1634x; 1.1634x over previous
#include <cuda_runtime.h>

#define TPB        256
#define DMODEL     1024
#define NEXP       8
#define TOKENS_TOT 32768
#define TPBLK      32
#define NBLOCKS    (TOKENS_TOT / TPBLK)   // 1024

typedef unsigned long long ull;

// ---------- packed fp32x2 helpers (sm_103a FFMA2 path) ----------
__device__ __forceinline__ ull pack2(float lo, float hi) {
    ull d;
    asm("mov.b64 %0, {%1, %2};" : "=l"(d) : "f"(lo), "f"(hi));
    return d;
}
__device__ __forceinline__ void unpack2(ull v, float& lo, float& hi) {
    asm("mov.b64 {%0, %1}, %2;" : "=f"(lo), "=f"(hi) : "l"(v));
}
__device__ __forceinline__ ull ffma2(ull a, ull b, ull c) {
    ull d;
    asm("fma.rn.f32x2 %0, %1, %2, %3;" : "=l"(d) : "l"(a), "l"(b), "l"(c));
    return d;
}

// ---------- integer warp redux (sm_80+; f32 redux does NOT exist on sm_103) ----------
__device__ __forceinline__ unsigned redux_max_u32(unsigned v) {
    unsigned r;
    asm volatile("redux.sync.max.u32 %0, %1, 0xffffffff;" : "=r"(r) : "r"(v));
    return r;
}
__device__ __forceinline__ unsigned redux_min_u32(unsigned v) {
    unsigned r;
    asm volatile("redux.sync.min.u32 %0, %1, 0xffffffff;" : "=r"(r) : "r"(v));
    return r;
}

// Order-preserving float <-> u32 total-order map: u32 max == float max.
__device__ __forceinline__ unsigned fmono(float v) {
    unsigned u = __float_as_uint(v);
    return ((int)u < 0) ? ~u : (u ^ 0x80000000u);
}
__device__ __forceinline__ float fmono_inv(unsigned k) {
    return __uint_as_float(((int)k < 0) ? (k ^ 0x80000000u) : ~k);
}

// Epilogue for one token: bias + 8-warp combine + top-2 (lowest-index
// tie-break, matching lax.top_k) + 2-way softmax + scatter. rb points at the
// 64-float slab red[buf][tokpar]; layout [e*8 + warp].
__device__ __forceinline__ void epilogue(const float* __restrict__ rb,
                                         int token, float bval, int lane,
                                         float* __restrict__ out_w,
                                         float* __restrict__ out_i,
                                         int write_idx)
{
    const int e = lane & 7;
    const float4* p = (const float4*)(rb + (e << 3));
    float4 a = p[0], c = p[1];
    float L = bval + ((a.x + a.y) + (a.z + a.w)) + ((c.x + c.y) + (c.z + c.w));

    const unsigned key = fmono(L);
    unsigned k1 = redux_max_u32(key);
    unsigned i1 = redux_min_u32((key == k1) ? (unsigned)e : 0xFFu);
    unsigned key2 = ((unsigned)e == i1) ? 0u : key;   // 0 = mono(-inf class)
    unsigned k2 = redux_max_u32(key2);
    unsigned i2 = redux_min_u32((key2 == k2) ? (unsigned)e : 0xFFu);

    const float m1 = fmono_inv(k1);
    const float m2 = fmono_inv(k2);
    const float t   = __expf(m2 - m1);        // m2 <= m1 -> t in (0,1]
    const float inv = 1.0f / (1.0f + t);
    if (lane < 8) {
        float wgt = ((unsigned)e == i1) ? inv
                  : (((unsigned)e == i2) ? t * inv : 0.0f);
        out_w[token * 8 + e] = wgt;
    }
    if (lane == 0 && write_idx)
        *(float2*)(out_i + token * 2) = make_float2((float)i1, (float)i2);
}

// Thread t owns dims [4t,4t+4) with W[8][4] resident in registers. Token PAIRS
// per iteration: 32 FFMA2, one fused 18-shfl butterfly reduce, 2 STS, one
// barrier. Epilogue for the previous pair runs pre-barrier out of the other
// smem buffer, overlapping the current pair's compute.
__global__ void __launch_bounds__(TPB)
gating_kernel(const float* __restrict__ x, const float* __restrict__ W,
              const float* __restrict__ b, float* __restrict__ out_w,
              float* __restrict__ out_i, int write_idx)
{
    __shared__ float red[2][2][64];   // [buf][token parity][expert*8 + warp]

    const int tid  = threadIdx.x;
    const int lane = tid & 31;
    const int wid  = tid >> 5;

    // Resident W slice: 8 experts x 4 dims as f32x2 pairs (32 regs).
    ull wlo[NEXP], whi[NEXP];
#pragma unroll
    for (int e = 0; e < NEXP; e++) {
        float4 wv = *(const float4*)(W + e * DMODEL + tid * 4);
        wlo[e] = pack2(wv.x, wv.y);
        whi[e] = pack2(wv.z, wv.w);
    }
    const float bval = b[lane & 7];

    const int t0 = blockIdx.x * TPBLK;
    const float4* xp = (const float4*)x + (size_t)t0 * (DMODEL / 4) + tid;

    // 4-token-deep prefetch (2 pairs in flight).
    float4 c0 = xp[0];
    float4 c1 = xp[256];
    float4 n0 = xp[512];
    float4 n1 = xp[768];

#pragma unroll 1
    for (int j = 0; j < TPBLK / 2; j++) {
        const ull xlo0 = pack2(c0.x, c0.y), xhi0 = pack2(c0.z, c0.w);
        const ull xlo1 = pack2(c1.x, c1.y), xhi1 = pack2(c1.z, c1.w);
        c0 = n0; c1 = n1;
        if (2 * j + 5 < TPBLK) {
            n0 = xp[(size_t)(2 * j + 4) * 256];
            n1 = xp[(size_t)(2 * j + 5) * 256];
        }

        // 16 independent 2-deep FFMA2 chains (2 tokens x 8 experts).
        float s0[NEXP], s1[NEXP];
#pragma unroll
        for (int e = 0; e < NEXP; e++) {
            ull a0 = ffma2(xlo0, wlo[e], 0ull); a0 = ffma2(xhi0, whi[e], a0);
            ull a1 = ffma2(xlo1, wlo[e], 0ull); a1 = ffma2(xhi1, whi[e], a1);
            float lo, hi;
            unpack2(a0, lo, hi); s0[e] = lo + hi;
            unpack2(a1, lo, hi); s1[e] = lo + hi;
        }

        // Fused 18-shfl butterfly: split experts over lane bits 4,3,2, then
        // sum dims over lane bits 1,0. Both tokens interleaved for ILP.
        const bool h16 = (lane & 16) != 0;
#pragma unroll
        for (int v = 0; v < 4; v++) {
            float d0 = __shfl_xor_sync(~0u, h16 ? s0[v] : s0[v + 4], 16);
            float d1 = __shfl_xor_sync(~0u, h16 ? s1[v] : s1[v + 4], 16);
            s0[v] = (h16 ? s0[v + 4] : s0[v]) + d0;
            s1[v] = (h16 ? s1[v + 4] : s1[v]) + d1;
        }
        const bool h8 = (lane & 8) != 0;
#pragma unroll
        for (int v = 0; v < 2; v++) {
            float d0 = __shfl_xor_sync(~0u, h8 ? s0[v] : s0[v + 2], 8);
            float d1 = __shfl_xor_sync(~0u, h8 ? s1[v] : s1[v + 2], 8);
            s0[v] = (h8 ? s0[v + 2] : s0[v]) + d0;
            s1[v] = (h8 ? s1[v + 2] : s1[v]) + d1;
        }
        const bool h4 = (lane & 4) != 0;
        {
            float d0 = __shfl_xor_sync(~0u, h4 ? s0[0] : s0[1], 4);
            float d1 = __shfl_xor_sync(~0u, h4 ? s1[0] : s1[1], 4);
            s0[0] = (h4 ? s0[1] : s0[0]) + d0;
            s1[0] = (h4 ? s1[1] : s1[0]) + d1;
        }
        float r0 = s0[0], r1 = s1[0];
        r0 += __shfl_xor_sync(~0u, r0, 2);
        r1 += __shfl_xor_sync(~0u, r1, 2);
        r0 += __shfl_xor_sync(~0u, r0, 1);
        r1 += __shfl_xor_sync(~0u, r1, 1);

        const int buf = j & 1;
        if ((lane & 3) == 0) {
            const int slot = (((lane >> 2) & 7) << 3) + wid;
            red[buf][0][slot] = r0;
            red[buf][1][slot] = r1;
        }

        // Epilogue for the PREVIOUS pair (other buffer) — independent of this
        // pair's reduce; overlaps it. Two warps, one token each, rotating.
        if (j > 0) {
            const int pbase = ((j - 1) * 2) & 7;    // 0,2,4,6,0,...
            if (wid == pbase)
                epilogue(red[buf ^ 1][0], t0 + 2 * j - 2, bval, lane,
                         out_w, out_i, write_idx);
            else if (wid == pbase + 1)
                epilogue(red[buf ^ 1][1], t0 + 2 * j - 1, bval, lane,
                         out_w, out_i, write_idx);
        }
        __syncthreads();
    }

    // Tail: last pair (tokens t0+30, t0+31) lives in buf 1.
    {
        const int pbase = (TPBLK - 2) & 7;          // 6
        const int buf   = (TPBLK / 2 - 1) & 1;      // 1
        if (wid == pbase)
            epilogue(red[buf][0], t0 + TPBLK - 2, bval, lane,
                     out_w, out_i, write_idx);
        else if (wid == pbase + 1)
            epilogue(red[buf][1], t0 + TPBLK - 1, bval, lane,
                     out_w, out_i, write_idx);
    }
}

extern "C" void kernel_launch(void* const* d_in, const int* in_sizes, int n_in,
                              void* d_out, int out_size)
{
    const float* x = nullptr; const float* W = nullptr; const float* b = nullptr;
    for (int i = 0; i < n_in; i++) {
        if (in_sizes[i] == NEXP)                b = (const float*)d_in[i];
        else if (in_sizes[i] == NEXP * DMODEL)  W = (const float*)d_in[i];
        else                                    x = (const float*)d_in[i];
    }

    float* ow = (float*)d_out;                       // weights: [B,S,E] f32
    float* oi = ow + (size_t)TOKENS_TOT * NEXP;      // indices (as f32): [B,S,2]
    const int need = TOKENS_TOT * NEXP + TOKENS_TOT * 2;
    const int write_idx = (out_size >= need) ? 1 : 0;

    gating_kernel<<<NBLOCKS, TPB>>>(x, W, b, ow, oi, write_idx);
}

// round 6
// speedup vs baseline: 1.6500x; 1.4183x over previous
#include <cuda_runtime.h>

#define DMODEL     1024
#define NEXP       8
#define TOKENS_TOT 32768
#define TPB        128
#define WARPS      4            // per CTA
#define TPW        16           // tokens per warp
#define TPG        4            // tokens per group (inner batch)
#define NGRP       (TPW / TPG)  // 4
#define NBLOCKS    (TOKENS_TOT / (WARPS * TPW))   // 512

typedef unsigned long long ull;

// ---------- packed fp32x2 helpers (sm_103a FFMA2 path) ----------
__device__ __forceinline__ ull pack2(float lo, float hi) {
    ull d;
    asm("mov.b64 %0, {%1, %2};" : "=l"(d) : "f"(lo), "f"(hi));
    return d;
}
__device__ __forceinline__ void unpack2(ull v, float& lo, float& hi) {
    asm("mov.b64 {%0, %1}, %2;" : "=f"(lo), "=f"(hi) : "l"(v));
}
__device__ __forceinline__ ull ffma2(ull a, ull b, ull c) {
    ull d;
    asm("fma.rn.f32x2 %0, %1, %2, %3;" : "=l"(d) : "l"(a), "l"(b), "l"(c));
    return d;
}

// ---------- integer warp redux (f32 redux does NOT exist on sm_103) ----------
__device__ __forceinline__ unsigned redux_max_u32(unsigned v) {
    unsigned r;
    asm volatile("redux.sync.max.u32 %0, %1, 0xffffffff;" : "=r"(r) : "r"(v));
    return r;
}
__device__ __forceinline__ unsigned redux_min_u32(unsigned v) {
    unsigned r;
    asm volatile("redux.sync.min.u32 %0, %1, 0xffffffff;" : "=r"(r) : "r"(v));
    return r;
}

// Order-preserving float <-> u32 total-order map: u32 max == float max.
__device__ __forceinline__ unsigned fmono(float v) {
    unsigned u = __float_as_uint(v);
    return ((int)u < 0) ? ~u : (u ^ 0x80000000u);
}
__device__ __forceinline__ float fmono_inv(unsigned k) {
    return __uint_as_float(((int)k < 0) ? (k ^ 0x80000000u) : ~k);
}

// Warp-autonomous gating: lane owns dims {c*128 + lane*4 .. +4 | c=0..7} so a
// single warp spans all 1024 dims of a token. W staged once in SMEM (32 KB),
// re-read per chunk amortized over 4 tokens. Per group of 4 tokens:
// 8 chunks x (4 LDG.128 + 8 LDS.128 + 64 FFMA2), then per token an in-warp
// 9-shfl butterfly (full logit) + redux top-2 epilogue. ZERO block barriers
// after staging.
__global__ void __launch_bounds__(TPB, 4)
gating_kernel(const float* __restrict__ x, const float* __restrict__ W,
              const float* __restrict__ b, float* __restrict__ out_w,
              float* __restrict__ out_i, int write_idx)
{
    __shared__ float4 Ws[NEXP * 256];   // 8 x 1024 floats = 32 KB

    const int tid  = threadIdx.x;
    const int lane = tid & 31;
    const int wid  = tid >> 5;

    // Stage W: 2048 float4 / 128 threads = 16 each.
    {
        const float4* Wv = (const float4*)W;
#pragma unroll
        for (int i = 0; i < 16; i++)
            Ws[tid + i * TPB] = Wv[tid + i * TPB];
    }
    __syncthreads();   // the only block barrier in the kernel

    const int   elane = (lane >> 2) & 7;      // expert this lane ends up with
    const float bval  = b[elane];

    const int t0 = (blockIdx.x * WARPS + wid) * TPW;
    const float4* xp4 = (const float4*)x + (size_t)t0 * 256 + lane;
    // token (g*4+t), chunk c lives at xp4[(g*4+t)*256 + c*32]

    // Prologue: load group 0, chunk 0 for 4 tokens.
    float4 xn0 = xp4[0 * 256];
    float4 xn1 = xp4[1 * 256];
    float4 xn2 = xp4[2 * 256];
    float4 xn3 = xp4[3 * 256];

#pragma unroll 1
    for (int g = 0; g < NGRP; g++) {
        ull acc[NEXP][TPG];
#pragma unroll
        for (int e = 0; e < NEXP; e++)
#pragma unroll
            for (int t = 0; t < TPG; t++) acc[e][t] = 0ull;

        const int gbase = g * TPG * 256;

#pragma unroll
        for (int c = 0; c < 8; c++) {
            // Consume prefetched x into packed form (this is the stall point).
            ull xlo[TPG], xhi[TPG];
            xlo[0] = pack2(xn0.x, xn0.y); xhi[0] = pack2(xn0.z, xn0.w);
            xlo[1] = pack2(xn1.x, xn1.y); xhi[1] = pack2(xn1.z, xn1.w);
            xlo[2] = pack2(xn2.x, xn2.y); xhi[2] = pack2(xn2.z, xn2.w);
            xlo[3] = pack2(xn3.x, xn3.y); xhi[3] = pack2(xn3.z, xn3.w);

            // Prefetch next chunk (or next group's chunk 0).
            if (c < 7) {
                const int o = gbase + (c + 1) * 32;
                xn0 = xp4[o + 0 * 256]; xn1 = xp4[o + 1 * 256];
                xn2 = xp4[o + 2 * 256]; xn3 = xp4[o + 3 * 256];
            } else if (g < NGRP - 1) {
                const int o = (g + 1) * TPG * 256;
                xn0 = xp4[o + 0 * 256]; xn1 = xp4[o + 1 * 256];
                xn2 = xp4[o + 2 * 256]; xn3 = xp4[o + 3 * 256];
            }

            // W for this chunk, 4 experts at a time (keeps W regs transient).
            const int wbase = c * 32 + lane;
#pragma unroll
            for (int eb = 0; eb < NEXP; eb += 4) {
                float4 w0 = Ws[(eb + 0) * 256 + wbase];
                float4 w1 = Ws[(eb + 1) * 256 + wbase];
                float4 w2 = Ws[(eb + 2) * 256 + wbase];
                float4 w3 = Ws[(eb + 3) * 256 + wbase];
                ull wl0 = pack2(w0.x, w0.y), wh0 = pack2(w0.z, w0.w);
                ull wl1 = pack2(w1.x, w1.y), wh1 = pack2(w1.z, w1.w);
                ull wl2 = pack2(w2.x, w2.y), wh2 = pack2(w2.z, w2.w);
                ull wl3 = pack2(w3.x, w3.y), wh3 = pack2(w3.z, w3.w);
#pragma unroll
                for (int t = 0; t < TPG; t++) {
                    acc[eb + 0][t] = ffma2(xhi[t], wh0, ffma2(xlo[t], wl0, acc[eb + 0][t]));
                    acc[eb + 1][t] = ffma2(xhi[t], wh1, ffma2(xlo[t], wl1, acc[eb + 1][t]));
                    acc[eb + 2][t] = ffma2(xhi[t], wh2, ffma2(xlo[t], wl2, acc[eb + 2][t]));
                    acc[eb + 3][t] = ffma2(xhi[t], wh3, ffma2(xlo[t], wl3, acc[eb + 3][t]));
                }
            }
        }

        // Finalize + epilogue per token, fully in-warp.
#pragma unroll
        for (int t = 0; t < TPG; t++) {
            float s[NEXP];
#pragma unroll
            for (int e = 0; e < NEXP; e++) {
                float lo, hi; unpack2(acc[e][t], lo, hi);
                s[e] = lo + hi;
            }

            // 9-shfl butterfly: experts over lane bits 4,3,2; dims over 1,0.
            const bool h16 = (lane & 16) != 0;
#pragma unroll
            for (int v = 0; v < 4; v++) {
                float d = __shfl_xor_sync(~0u, h16 ? s[v] : s[v + 4], 16);
                s[v] = (h16 ? s[v + 4] : s[v]) + d;
            }
            const bool h8 = (lane & 8) != 0;
#pragma unroll
            for (int v = 0; v < 2; v++) {
                float d = __shfl_xor_sync(~0u, h8 ? s[v] : s[v + 2], 8);
                s[v] = (h8 ? s[v + 2] : s[v]) + d;
            }
            const bool h4 = (lane & 4) != 0;
            {
                float d = __shfl_xor_sync(~0u, h4 ? s[0] : s[1], 4);
                s[0] = (h4 ? s[1] : s[0]) + d;
            }
            float r = s[0];
            r += __shfl_xor_sync(~0u, r, 2);
            r += __shfl_xor_sync(~0u, r, 1);

            // Lane now holds the complete logit for expert `elane` (x4 copies).
            const float L = r + bval;
            const unsigned key = fmono(L);
            unsigned k1 = redux_max_u32(key);
            unsigned i1 = redux_min_u32((key == k1) ? (unsigned)elane : 0xFFu);
            unsigned key2 = ((unsigned)elane == i1) ? 0u : key;
            unsigned k2 = redux_max_u32(key2);
            unsigned i2 = redux_min_u32((key2 == k2) ? (unsigned)elane : 0xFFu);

            const float m1 = fmono_inv(k1);
            const float m2 = fmono_inv(k2);
            const float tt  = __expf(m2 - m1);     // m2 <= m1 -> (0,1]
            const float inv = 1.0f / (1.0f + tt);

            const int token = t0 + g * TPG + t;
            if ((lane & 3) == 0) {
                float wgt = ((unsigned)elane == i1) ? inv
                          : (((unsigned)elane == i2) ? tt * inv : 0.0f);
                out_w[token * 8 + elane] = wgt;
            }
            if (lane == t * 8 && write_idx)
                *(float2*)(out_i + token * 2) =
                    make_float2((float)i1, (float)i2);
        }
    }
}

extern "C" void kernel_launch(void* const* d_in, const int* in_sizes, int n_in,
                              void* d_out, int out_size)
{
    const float* x = nullptr; const float* W = nullptr; const float* b = nullptr;
    for (int i = 0; i < n_in; i++) {
        if (in_sizes[i] == NEXP)                b = (const float*)d_in[i];
        else if (in_sizes[i] == NEXP * DMODEL)  W = (const float*)d_in[i];
        else                                    x = (const float*)d_in[i];
    }

    float* ow = (float*)d_out;                       // weights: [B,S,E] f32
    float* oi = ow + (size_t)TOKENS_TOT * NEXP;      // indices (as f32): [B,S,2]
    const int need = TOKENS_TOT * NEXP + TOKENS_TOT * 2;
    const int write_idx = (out_size >= need) ? 1 : 0;

    gating_kernel<<<NBLOCKS, TPB>>>(x, W, b, ow, oi, write_idx);
}

// round 7
// speedup vs baseline: 1.6516x; 1.0010x over previous
#include <cuda_runtime.h>

#define DMODEL     1024
#define NEXP       8
#define TOKENS_TOT 32768
#define TPB        128
#define WARPS      4            // per CTA
#define TPW        16           // tokens per warp
#define TPG        4            // tokens per group (inner batch)
#define NGRP       (TPW / TPG)  // 4
#define NBLOCKS    (TOKENS_TOT / (WARPS * TPW))   // 512

typedef unsigned long long ull;

// ---------- packed fp32x2 helpers (sm_103a FFMA2 path) ----------
__device__ __forceinline__ ull pack2(float lo, float hi) {
    ull d;
    asm("mov.b64 %0, {%1, %2};" : "=l"(d) : "f"(lo), "f"(hi));
    return d;
}
__device__ __forceinline__ void unpack2(ull v, float& lo, float& hi) {
    asm("mov.b64 {%0, %1}, %2;" : "=f"(lo), "=f"(hi) : "l"(v));
}
__device__ __forceinline__ ull ffma2(ull a, ull b, ull c) {
    ull d;
    asm("fma.rn.f32x2 %0, %1, %2, %3;" : "=l"(d) : "l"(a), "l"(b), "l"(c));
    return d;
}

// ---------- integer warp redux (f32 redux does NOT exist on sm_103) ----------
__device__ __forceinline__ unsigned redux_max_u32(unsigned v) {
    unsigned r;
    asm volatile("redux.sync.max.u32 %0, %1, 0xffffffff;" : "=r"(r) : "r"(v));
    return r;
}
__device__ __forceinline__ unsigned redux_min_u32(unsigned v) {
    unsigned r;
    asm volatile("redux.sync.min.u32 %0, %1, 0xffffffff;" : "=r"(r) : "r"(v));
    return r;
}

// Order-preserving float <-> u32 total-order map: u32 max == float max.
__device__ __forceinline__ unsigned fmono(float v) {
    unsigned u = __float_as_uint(v);
    return ((int)u < 0) ? ~u : (u ^ 0x80000000u);
}
__device__ __forceinline__ float fmono_inv(unsigned k) {
    return __uint_as_float(((int)k < 0) ? (k ^ 0x80000000u) : ~k);
}

// Warp-autonomous gating: lane owns dims {c*128 + lane*4 .. +4 | c=0..7} so a
// single warp spans all 1024 dims of a token. W staged once in SMEM (32 KB),
// re-read per chunk amortized over 4 tokens. Per group of 4 tokens:
// 8 chunks x (4 LDG.128 + 8 LDS.128 + 64 FFMA2), then per token an in-warp
// 9-shfl butterfly (full logit) + redux top-2 epilogue. ZERO block barriers
// after staging.
__global__ void __launch_bounds__(TPB, 4)
gating_kernel(const float* __restrict__ x, const float* __restrict__ W,
              const float* __restrict__ b, float* __restrict__ out_w,
              float* __restrict__ out_i, int write_idx)
{
    __shared__ float4 Ws[NEXP * 256];   // 8 x 1024 floats = 32 KB

    const int tid  = threadIdx.x;
    const int lane = tid & 31;
    const int wid  = tid >> 5;

    // Stage W: 2048 float4 / 128 threads = 16 each.
    {
        const float4* Wv = (const float4*)W;
#pragma unroll
        for (int i = 0; i < 16; i++)
            Ws[tid + i * TPB] = Wv[tid + i * TPB];
    }
    __syncthreads();   // the only block barrier in the kernel

    const int   elane = (lane >> 2) & 7;      // expert this lane ends up with
    const float bval  = b[elane];

    const int t0 = (blockIdx.x * WARPS + wid) * TPW;
    const float4* xp4 = (const float4*)x + (size_t)t0 * 256 + lane;
    // token (g*4+t), chunk c lives at xp4[(g*4+t)*256 + c*32]

    // Prologue: load group 0, chunk 0 for 4 tokens.
    float4 xn0 = xp4[0 * 256];
    float4 xn1 = xp4[1 * 256];
    float4 xn2 = xp4[2 * 256];
    float4 xn3 = xp4[3 * 256];

#pragma unroll 1
    for (int g = 0; g < NGRP; g++) {
        ull acc[NEXP][TPG];
#pragma unroll
        for (int e = 0; e < NEXP; e++)
#pragma unroll
            for (int t = 0; t < TPG; t++) acc[e][t] = 0ull;

        const int gbase = g * TPG * 256;

#pragma unroll
        for (int c = 0; c < 8; c++) {
            // Consume prefetched x into packed form (this is the stall point).
            ull xlo[TPG], xhi[TPG];
            xlo[0] = pack2(xn0.x, xn0.y); xhi[0] = pack2(xn0.z, xn0.w);
            xlo[1] = pack2(xn1.x, xn1.y); xhi[1] = pack2(xn1.z, xn1.w);
            xlo[2] = pack2(xn2.x, xn2.y); xhi[2] = pack2(xn2.z, xn2.w);
            xlo[3] = pack2(xn3.x, xn3.y); xhi[3] = pack2(xn3.z, xn3.w);

            // Prefetch next chunk (or next group's chunk 0).
            if (c < 7) {
                const int o = gbase + (c + 1) * 32;
                xn0 = xp4[o + 0 * 256]; xn1 = xp4[o + 1 * 256];
                xn2 = xp4[o + 2 * 256]; xn3 = xp4[o + 3 * 256];
            } else if (g < NGRP - 1) {
                const int o = (g + 1) * TPG * 256;
                xn0 = xp4[o + 0 * 256]; xn1 = xp4[o + 1 * 256];
                xn2 = xp4[o + 2 * 256]; xn3 = xp4[o + 3 * 256];
            }

            // W for this chunk, 4 experts at a time (keeps W regs transient).
            const int wbase = c * 32 + lane;
#pragma unroll
            for (int eb = 0; eb < NEXP; eb += 4) {
                float4 w0 = Ws[(eb + 0) * 256 + wbase];
                float4 w1 = Ws[(eb + 1) * 256 + wbase];
                float4 w2 = Ws[(eb + 2) * 256 + wbase];
                float4 w3 = Ws[(eb + 3) * 256 + wbase];
                ull wl0 = pack2(w0.x, w0.y), wh0 = pack2(w0.z, w0.w);
                ull wl1 = pack2(w1.x, w1.y), wh1 = pack2(w1.z, w1.w);
                ull wl2 = pack2(w2.x, w2.y), wh2 = pack2(w2.z, w2.w);
                ull wl3 = pack2(w3.x, w3.y), wh3 = pack2(w3.z, w3.w);
#pragma unroll
                for (int t = 0; t < TPG; t++) {
                    acc[eb + 0][t] = ffma2(xhi[t], wh0, ffma2(xlo[t], wl0, acc[eb + 0][t]));
                    acc[eb + 1][t] = ffma2(xhi[t], wh1, ffma2(xlo[t], wl1, acc[eb + 1][t]));
                    acc[eb + 2][t] = ffma2(xhi[t], wh2, ffma2(xlo[t], wl2, acc[eb + 2][t]));
                    acc[eb + 3][t] = ffma2(xhi[t], wh3, ffma2(xlo[t], wl3, acc[eb + 3][t]));
                }
            }
        }

        // Finalize + epilogue per token, fully in-warp.
#pragma unroll
        for (int t = 0; t < TPG; t++) {
            float s[NEXP];
#pragma unroll
            for (int e = 0; e < NEXP; e++) {
                float lo, hi; unpack2(acc[e][t], lo, hi);
                s[e] = lo + hi;
            }

            // 9-shfl butterfly: experts over lane bits 4,3,2; dims over 1,0.
            const bool h16 = (lane & 16) != 0;
#pragma unroll
            for (int v = 0; v < 4; v++) {
                float d = __shfl_xor_sync(~0u, h16 ? s[v] : s[v + 4], 16);
                s[v] = (h16 ? s[v + 4] : s[v]) + d;
            }
            const bool h8 = (lane & 8) != 0;
#pragma unroll
            for (int v = 0; v < 2; v++) {
                float d = __shfl_xor_sync(~0u, h8 ? s[v] : s[v + 2], 8);
                s[v] = (h8 ? s[v + 2] : s[v]) + d;
            }
            const bool h4 = (lane & 4) != 0;
            {
                float d = __shfl_xor_sync(~0u, h4 ? s[0] : s[1], 4);
                s[0] = (h4 ? s[1] : s[0]) + d;
            }
            float r = s[0];
            r += __shfl_xor_sync(~0u, r, 2);
            r += __shfl_xor_sync(~0u, r, 1);

            // Lane now holds the complete logit for expert `elane` (x4 copies).
            const float L = r + bval;
            const unsigned key = fmono(L);
            unsigned k1 = redux_max_u32(key);
            unsigned i1 = redux_min_u32((key == k1) ? (unsigned)elane : 0xFFu);
            unsigned key2 = ((unsigned)elane == i1) ? 0u : key;
            unsigned k2 = redux_max_u32(key2);
            unsigned i2 = redux_min_u32((key2 == k2) ? (unsigned)elane : 0xFFu);

            const float m1 = fmono_inv(k1);
            const float m2 = fmono_inv(k2);
            const float tt  = __expf(m2 - m1);     // m2 <= m1 -> (0,1]
            const float inv = 1.0f / (1.0f + tt);

            const int token = t0 + g * TPG + t;
            if ((lane & 3) == 0) {
                float wgt = ((unsigned)elane == i1) ? inv
                          : (((unsigned)elane == i2) ? tt * inv : 0.0f);
                out_w[token * 8 + elane] = wgt;
            }
            if (lane == t * 8 && write_idx)
                *(float2*)(out_i + token * 2) =
                    make_float2((float)i1, (float)i2);
        }
    }
}

extern "C" void kernel_launch(void* const* d_in, const int* in_sizes, int n_in,
                              void* d_out, int out_size)
{
    const float* x = nullptr; const float* W = nullptr; const float* b = nullptr;
    for (int i = 0; i < n_in; i++) {
        if (in_sizes[i] == NEXP)                b = (const float*)d_in[i];
        else if (in_sizes[i] == NEXP * DMODEL)  W = (const float*)d_in[i];
        else                                    x = (const float*)d_in[i];
    }

    float* ow = (float*)d_out;                       // weights: [B,S,E] f32
    float* oi = ow + (size_t)TOKENS_TOT * NEXP;      // indices (as f32): [B,S,2]
    const int need = TOKENS_TOT * NEXP + TOKENS_TOT * 2;
    const int write_idx = (out_size >= need) ? 1 : 0;

    gating_kernel<<<NBLOCKS, TPB>>>(x, W, b, ow, oi, write_idx);
}